// round 2
// baseline (speedup 1.0000x reference)
#include <cuda_runtime.h>
#include <math.h>

#define BB   4
#define TT   2048
#define EMB_ 1024
#define HH   8
#define HD   64      // head dim
#define NQK  512     // H*HD
#define BH   32      // B*H

// Scratch (device globals: no allocation allowed in kernel_launch)
__device__ float g_q[BH * TT * HD];      // (b*H+h, t, hd), pre-scaled
__device__ float g_k[BH * TT * HD];      // pre-scaled
__device__ float g_v[BH * TT * HD];
__device__ float g_att[BB * TT * NQK];   // (b, t, h*hd)

// ---------------------------------------------------------------------------
// Kernel 1: QKV projection.  y = X @ W, split heads, optional scale.
// grid (NQK/64, B*T/64, 3), block 256 (16x16, 4x4 microtile)
// ---------------------------------------------------------------------------
__global__ __launch_bounds__(256) void qkv_kernel(
    const float* __restrict__ X,
    const float* __restrict__ Wq, const float* __restrict__ Wk,
    const float* __restrict__ Wv)
{
    __shared__ float As[16][68];   // [k][m]
    __shared__ float Bs[16][68];   // [k][n]

    const int z = blockIdx.z;
    const float* __restrict__ W = (z == 0) ? Wq : ((z == 1) ? Wk : Wv);
    float* __restrict__ Out = (z == 0) ? g_q : ((z == 1) ? g_k : g_v);
    const float scale = (z == 2) ? 1.0f : 0.35355339059327373f;  // 1/64^0.25

    const int m0 = blockIdx.y << 6;
    const int n0 = blockIdx.x << 6;
    const int tid = threadIdx.x;
    const int ty = tid >> 4, tx = tid & 15;

    const int lm  = tid >> 2;          // 0..63
    const int lk4 = (tid & 3) << 2;    // 0,4,8,12
    const int bk  = tid >> 4;          // 0..15
    const int bn4 = (tid & 15) << 2;   // 0..60

    float acc[4][4] = {};

    for (int k0 = 0; k0 < EMB_; k0 += 16) {
        float4 xa = *(const float4*)&X[(m0 + lm) * EMB_ + k0 + lk4];
        float4 wb = *(const float4*)&W[(k0 + bk) * NQK + n0 + bn4];
        __syncthreads();
        As[lk4 + 0][lm] = xa.x;
        As[lk4 + 1][lm] = xa.y;
        As[lk4 + 2][lm] = xa.z;
        As[lk4 + 3][lm] = xa.w;
        *(float4*)&Bs[bk][bn4] = wb;
        __syncthreads();
#pragma unroll
        for (int kk = 0; kk < 16; kk++) {
            float4 a = *(const float4*)&As[kk][ty << 2];
            float4 b = *(const float4*)&Bs[kk][tx << 2];
            acc[0][0] += a.x * b.x; acc[0][1] += a.x * b.y; acc[0][2] += a.x * b.z; acc[0][3] += a.x * b.w;
            acc[1][0] += a.y * b.x; acc[1][1] += a.y * b.y; acc[1][2] += a.y * b.z; acc[1][3] += a.y * b.w;
            acc[2][0] += a.z * b.x; acc[2][1] += a.z * b.y; acc[2][2] += a.z * b.z; acc[2][3] += a.z * b.w;
            acc[3][0] += a.w * b.x; acc[3][1] += a.w * b.y; acc[3][2] += a.w * b.z; acc[3][3] += a.w * b.w;
        }
    }

    const int h = n0 >> 6;             // block covers exactly one head
#pragma unroll
    for (int r = 0; r < 4; r++) {
        int m  = m0 + (ty << 2) + r;
        int bb = m >> 11;              // T = 2048
        int t  = m & (TT - 1);
        float4 o4 = make_float4(acc[r][0] * scale, acc[r][1] * scale,
                                acc[r][2] * scale, acc[r][3] * scale);
        *(float4*)&Out[(((bb * HH) + h) * TT + t) * HD + (tx << 2)] = o4;
    }
}

// ---------------------------------------------------------------------------
// Kernel 2: flash attention, 64-query tile per block.
// grid (T/64, BH), block 256 (16x16, 4x4 microtile)
// Swizzled smem layout for transposed Q/K (and P reusing the K buffer):
//   element (a=row, b=col) of a 64x64 tile -> a*64 + (((b>>2)^(a>>2))&15)*4 + (b&3)
// ---------------------------------------------------------------------------
__device__ __forceinline__ int swz_idx(int a, int b) {
    return (a << 6) | ((((b >> 2) ^ (a >> 2)) & 15) << 2) | (b & 3);
}

__global__ __launch_bounds__(256) void attn_kernel(const int* __restrict__ pads)
{
    __shared__ float Qst[64 * 64];   // [hd][qrow], swizzled
    __shared__ float Kst[64 * 64];   // [hd][keycol] swizzled; reused as P [qrow][key]
    __shared__ float Vs [64 * 64];   // [keyrow][hd], plain

    const int bh  = blockIdx.y;
    const int q0  = blockIdx.x << 6;
    const int tid = threadIdx.x;
    const int ty  = tid >> 4, tx = tid & 15;

    const float* __restrict__ Qp = g_q + bh * (TT * HD);
    const float* __restrict__ Kp = g_k + bh * (TT * HD);
    const float* __restrict__ Vp = g_v + bh * (TT * HD);

    int thr = TT + 1;                  // "no masking"
    if (bh < BB) thr = TT - pads[bh];  // faithful to reference: only first B slices

    // Load Q tile, transposed + swizzled
    {
        const int row = tid >> 2;
#pragma unroll
        for (int j = 0; j < 4; j++) {
            int c4 = ((tid & 3) + (j << 2)) << 2;
            float4 qf = *(const float4*)&Qp[(q0 + row) * HD + c4];
            Qst[swz_idx(c4 + 0, row)] = qf.x;
            Qst[swz_idx(c4 + 1, row)] = qf.y;
            Qst[swz_idx(c4 + 2, row)] = qf.z;
            Qst[swz_idx(c4 + 3, row)] = qf.w;
        }
    }

    float o[4][4] = {};
    float mi[4] = {-1e30f, -1e30f, -1e30f, -1e30f};
    float li[4] = {};

    for (int j0 = 0; j0 < TT; j0 += 64) {
        // Load K (transposed+swizzled) and V (plain) tiles
        {
            const int row = tid >> 2;
#pragma unroll
            for (int j = 0; j < 4; j++) {
                int c4 = ((tid & 3) + (j << 2)) << 2;
                float4 kf = *(const float4*)&Kp[(j0 + row) * HD + c4];
                float4 vf = *(const float4*)&Vp[(j0 + row) * HD + c4];
                Kst[swz_idx(c4 + 0, row)] = kf.x;
                Kst[swz_idx(c4 + 1, row)] = kf.y;
                Kst[swz_idx(c4 + 2, row)] = kf.z;
                Kst[swz_idx(c4 + 3, row)] = kf.w;
                *(float4*)&Vs[(row << 6) + c4] = vf;
            }
        }
        __syncthreads();

        // S = Q @ K^T (scaled already)
        float s[4][4] = {};
#pragma unroll 8
        for (int kk = 0; kk < 64; kk++) {
            int g = (kk >> 2) & 15;
            float4 a = *(const float4*)&Qst[(kk << 6) + (((ty ^ g) & 15) << 2)];
            float4 b = *(const float4*)&Kst[(kk << 6) + (((tx ^ g) & 15) << 2)];
            s[0][0] += a.x * b.x; s[0][1] += a.x * b.y; s[0][2] += a.x * b.z; s[0][3] += a.x * b.w;
            s[1][0] += a.y * b.x; s[1][1] += a.y * b.y; s[1][2] += a.y * b.z; s[1][3] += a.y * b.w;
            s[2][0] += a.z * b.x; s[2][1] += a.z * b.y; s[2][2] += a.z * b.z; s[2][3] += a.z * b.w;
            s[3][0] += a.w * b.x; s[3][1] += a.w * b.y; s[3][2] += a.w * b.z; s[3][3] += a.w * b.w;
        }

        // Mask (row>=thr && col>=thr)
        if (j0 + 64 > thr) {
#pragma unroll
            for (int r = 0; r < 4; r++) {
                int gi = q0 + (ty << 2) + r;
                if (gi >= thr) {
#pragma unroll
                    for (int c = 0; c < 4; c++)
                        if (j0 + (tx << 2) + c >= thr) s[r][c] = -1e30f;
                }
            }
        }

        // Online softmax update (row groups are 16 contiguous lanes)
#pragma unroll
        for (int r = 0; r < 4; r++) {
            float v = fmaxf(fmaxf(s[r][0], s[r][1]), fmaxf(s[r][2], s[r][3]));
            v = fmaxf(v, __shfl_xor_sync(0xffffffffu, v, 1));
            v = fmaxf(v, __shfl_xor_sync(0xffffffffu, v, 2));
            v = fmaxf(v, __shfl_xor_sync(0xffffffffu, v, 4));
            v = fmaxf(v, __shfl_xor_sync(0xffffffffu, v, 8));
            float mnew  = fmaxf(mi[r], v);
            float alpha = __expf(mi[r] - mnew);
            float sum = 0.f;
#pragma unroll
            for (int c = 0; c < 4; c++) {
                s[r][c] = __expf(s[r][c] - mnew);
                sum += s[r][c];
            }
            sum += __shfl_xor_sync(0xffffffffu, sum, 1);
            sum += __shfl_xor_sync(0xffffffffu, sum, 2);
            sum += __shfl_xor_sync(0xffffffffu, sum, 4);
            sum += __shfl_xor_sync(0xffffffffu, sum, 8);
            li[r] = li[r] * alpha + sum;
            mi[r] = mnew;
            o[r][0] *= alpha; o[r][1] *= alpha; o[r][2] *= alpha; o[r][3] *= alpha;
        }

        __syncthreads();   // all warps done reading Kst before reuse as P

        // Store P (reuse Kst), layout [qrow][key] swizzled
#pragma unroll
        for (int r = 0; r < 4; r++) {
            int qrow = (ty << 2) + r;
            int g = (tx ^ (qrow >> 2)) & 15;
            *(float4*)&Kst[(qrow << 6) + (g << 2)] =
                make_float4(s[r][0], s[r][1], s[r][2], s[r][3]);
        }
        __syncthreads();

        // O += P @ V
#pragma unroll 4
        for (int kk4 = 0; kk4 < 64; kk4 += 4) {
            float4 p[4];
#pragma unroll
            for (int r = 0; r < 4; r++) {
                int qrow = (ty << 2) + r;
                int g = ((kk4 >> 2) ^ (qrow >> 2)) & 15;
                p[r] = *(const float4*)&Kst[(qrow << 6) + (g << 2)];
            }
            float4 b0 = *(const float4*)&Vs[((kk4 + 0) << 6) + (tx << 2)];
            float4 b1 = *(const float4*)&Vs[((kk4 + 1) << 6) + (tx << 2)];
            float4 b2 = *(const float4*)&Vs[((kk4 + 2) << 6) + (tx << 2)];
            float4 b3 = *(const float4*)&Vs[((kk4 + 3) << 6) + (tx << 2)];
#pragma unroll
            for (int r = 0; r < 4; r++) {
                o[r][0] += p[r].x * b0.x + p[r].y * b1.x + p[r].z * b2.x + p[r].w * b3.x;
                o[r][1] += p[r].x * b0.y + p[r].y * b1.y + p[r].z * b2.y + p[r].w * b3.y;
                o[r][2] += p[r].x * b0.z + p[r].y * b1.z + p[r].z * b2.z + p[r].w * b3.z;
                o[r][3] += p[r].x * b0.w + p[r].y * b1.w + p[r].z * b2.w + p[r].w * b3.w;
            }
        }
        __syncthreads();   // before next tile overwrites Kst/Vs
    }

    // Epilogue: O / l, write to (b, t, h*HD + kd)
    const int b = bh >> 3;    // H = 8
    const int h = bh & 7;
#pragma unroll
    for (int r = 0; r < 4; r++) {
        int t = q0 + (ty << 2) + r;
        float inv = 1.0f / li[r];
        float4 res = make_float4(o[r][0] * inv, o[r][1] * inv,
                                 o[r][2] * inv, o[r][3] * inv);
        *(float4*)&g_att[(b * TT + t) * NQK + (h << 6) + (tx << 2)] = res;
    }
}

// ---------------------------------------------------------------------------
// Kernel 3: out = g_att (8192x512) @ Wu (512x64) + bu
// grid (B*T/64), block 256
// ---------------------------------------------------------------------------
__global__ __launch_bounds__(256) void proj_kernel(
    const float* __restrict__ Wu, const float* __restrict__ bu,
    float* __restrict__ out)
{
    __shared__ float As[16][68];
    __shared__ float Bs[16][68];

    const int m0 = blockIdx.x << 6;
    const int tid = threadIdx.x;
    const int ty = tid >> 4, tx = tid & 15;

    const int lm  = tid >> 2;
    const int lk4 = (tid & 3) << 2;
    const int bk  = tid >> 4;
    const int bn4 = (tid & 15) << 2;

    float acc[4][4] = {};

    for (int k0 = 0; k0 < NQK; k0 += 16) {
        float4 xa = *(const float4*)&g_att[(m0 + lm) * NQK + k0 + lk4];
        float4 wb = *(const float4*)&Wu[(k0 + bk) * HD + bn4];
        __syncthreads();
        As[lk4 + 0][lm] = xa.x;
        As[lk4 + 1][lm] = xa.y;
        As[lk4 + 2][lm] = xa.z;
        As[lk4 + 3][lm] = xa.w;
        *(float4*)&Bs[bk][bn4] = wb;
        __syncthreads();
#pragma unroll
        for (int kk = 0; kk < 16; kk++) {
            float4 a = *(const float4*)&As[kk][ty << 2];
            float4 b = *(const float4*)&Bs[kk][tx << 2];
            acc[0][0] += a.x * b.x; acc[0][1] += a.x * b.y; acc[0][2] += a.x * b.z; acc[0][3] += a.x * b.w;
            acc[1][0] += a.y * b.x; acc[1][1] += a.y * b.y; acc[1][2] += a.y * b.z; acc[1][3] += a.y * b.w;
            acc[2][0] += a.z * b.x; acc[2][1] += a.z * b.y; acc[2][2] += a.z * b.z; acc[2][3] += a.z * b.w;
            acc[3][0] += a.w * b.x; acc[3][1] += a.w * b.y; acc[3][2] += a.w * b.z; acc[3][3] += a.w * b.w;
        }
    }

    float4 bias = *(const float4*)&bu[tx << 2];
#pragma unroll
    for (int r = 0; r < 4; r++) {
        int m = m0 + (ty << 2) + r;
        float4 res = make_float4(acc[r][0] + bias.x, acc[r][1] + bias.y,
                                 acc[r][2] + bias.z, acc[r][3] + bias.w);
        *(float4*)&out[m * HD + (tx << 2)] = res;
    }
}

// ---------------------------------------------------------------------------
extern "C" void kernel_launch(void* const* d_in, const int* in_sizes, int n_in,
                              void* d_out, int out_size)
{
    (void)in_sizes; (void)n_in; (void)out_size;
    const float* x    = (const float*)d_in[0];
    const int*   pads = (const int*)  d_in[1];
    const float* Wq   = (const float*)d_in[2];
    const float* Wk   = (const float*)d_in[3];
    const float* Wv   = (const float*)d_in[4];
    const float* Wu   = (const float*)d_in[5];
    const float* bu   = (const float*)d_in[6];
    float* out = (float*)d_out;

    dim3 g1(NQK / 64, (BB * TT) / 64, 3);
    qkv_kernel<<<g1, 256>>>(x, Wq, Wk, Wv);

    dim3 g2(TT / 64, BH);
    attn_kernel<<<g2, 256>>>(pads);

    proj_kernel<<<(BB * TT) / 64, 256>>>(Wu, bu, out);
}

// round 6
// speedup vs baseline: 2.5617x; 2.5617x over previous
#include <cuda_runtime.h>
#include <cuda_bf16.h>
#include <cstdint>
#include <math.h>

#define BB   4
#define TT   2048
#define EMB_ 1024
#define HH   8
#define HD   64
#define NQK  512
#define BH   32

// ---------------------------------------------------------------------------
// Device scratch
// ---------------------------------------------------------------------------
__device__ unsigned short g_xh[8192 * 1024];
__device__ unsigned short g_xl[8192 * 1024];
__device__ unsigned short g_wth[1536 * 1024];   // [z*512+n][k], scaled for z<2
__device__ unsigned short g_wtl[1536 * 1024];
__device__ unsigned short g_wuth[64 * 512];     // Wu^T [n][k]
__device__ unsigned short g_wutl[64 * 512];
__device__ unsigned short g_qh[BH * TT * HD];   // [bh][t][hd]
__device__ unsigned short g_ql[BH * TT * HD];
__device__ unsigned short g_kh[BH * TT * HD];
__device__ unsigned short g_kl[BH * TT * HD];
__device__ unsigned short g_vh[BH * TT * HD];
__device__ unsigned short g_vl[BH * TT * HD];
__device__ unsigned short g_ah[8192 * 512];     // attention out hi
__device__ unsigned short g_al[8192 * 512];

// ---------------------------------------------------------------------------
// Helpers (family-portable ISA only: mma.sync / ldmatrix / cp.async)
// ---------------------------------------------------------------------------
__device__ __forceinline__ uint32_t smem_u32(const void* p) {
    uint32_t a;
    asm("{ .reg .u64 t; cvta.to.shared.u64 t, %1; cvt.u32.u64 %0, t; }" : "=r"(a) : "l"(p));
    return a;
}
__device__ __forceinline__ void cpa16(uint32_t sm, const void* g) {
    asm volatile("cp.async.cg.shared.global [%0], [%1], 16;" :: "r"(sm), "l"(g));
}
#define CPA_COMMIT() asm volatile("cp.async.commit_group;" ::: "memory")
#define CPA_WAIT0()  asm volatile("cp.async.wait_group 0;" ::: "memory")

__device__ __forceinline__ void ldsm_x4(uint32_t* r, uint32_t a) {
    asm volatile("ldmatrix.sync.aligned.m8n8.x4.shared.b16 {%0,%1,%2,%3}, [%4];"
                 : "=r"(r[0]), "=r"(r[1]), "=r"(r[2]), "=r"(r[3]) : "r"(a));
}
__device__ __forceinline__ void ldsm_x4_t(uint32_t* r, uint32_t a) {
    asm volatile("ldmatrix.sync.aligned.m8n8.x4.trans.shared.b16 {%0,%1,%2,%3}, [%4];"
                 : "=r"(r[0]), "=r"(r[1]), "=r"(r[2]), "=r"(r[3]) : "r"(a));
}
__device__ __forceinline__ void mma_bf16(float* c, const uint32_t* a, uint32_t b0, uint32_t b1) {
    asm volatile("mma.sync.aligned.m16n8k16.row.col.f32.bf16.bf16.f32 "
                 "{%0,%1,%2,%3}, {%4,%5,%6,%7}, {%8,%9}, {%0,%1,%2,%3};"
                 : "+f"(c[0]), "+f"(c[1]), "+f"(c[2]), "+f"(c[3])
                 : "r"(a[0]), "r"(a[1]), "r"(a[2]), "r"(a[3]), "r"(b0), "r"(b1));
}
__device__ __forceinline__ uint32_t swz(uint32_t o) { return o ^ ((o >> 3) & 0x70); }

// pack (x0,x1) -> bf16x2 hi + bf16x2 residual-lo
__device__ __forceinline__ void split_pack(float x0, float x1, uint32_t& h, uint32_t& l) {
    asm("cvt.rn.bf16x2.f32 %0, %1, %2;" : "=r"(h) : "f"(x1), "f"(x0));
    float h0 = __uint_as_float(h << 16);
    float h1 = __uint_as_float(h & 0xffff0000u);
    float l0 = x0 - h0, l1 = x1 - h1;
    asm("cvt.rn.bf16x2.f32 %0, %1, %2;" : "=r"(l) : "f"(l1), "f"(l0));
}
__device__ __forceinline__ void split2(float x, unsigned short& h, unsigned short& l) {
    __nv_bfloat16 bh = __float2bfloat16(x);
    float lo = x - __bfloat162float(bh);
    __nv_bfloat16 bl = __float2bfloat16(lo);
    h = reinterpret_cast<unsigned short&>(bh);
    l = reinterpret_cast<unsigned short&>(bl);
}

// ---------------------------------------------------------------------------
// Split pre-passes
// ---------------------------------------------------------------------------
__global__ __launch_bounds__(256) void split_x_kernel(const float* __restrict__ X) {
    int i = (blockIdx.x * 256 + threadIdx.x) * 4;
    float4 v = *(const float4*)&X[i];
    uint32_t h0, l0, h1, l1;
    split_pack(v.x, v.y, h0, l0);
    split_pack(v.z, v.w, h1, l1);
    *(uint32_t*)&g_xh[i] = h0; *(uint32_t*)&g_xh[i + 2] = h1;
    *(uint32_t*)&g_xl[i] = l0; *(uint32_t*)&g_xl[i + 2] = l1;
}

__global__ __launch_bounds__(256) void split_w_kernel(
    const float* __restrict__ Wq, const float* __restrict__ Wk, const float* __restrict__ Wv) {
    __shared__ float tile[32][33];
    const int z = blockIdx.z;
    const float* W = (z == 0) ? Wq : ((z == 1) ? Wk : Wv);
    const float scale = (z == 2) ? 1.0f : 0.35355339059327373f;   // 1/64^0.25
    const int n0 = blockIdx.x * 32, k0 = blockIdx.y * 32;
    for (int i = threadIdx.x; i < 1024; i += 256) {
        int r = i >> 5, c = i & 31;
        tile[c][r] = W[(k0 + r) * 512 + n0 + c] * scale;
    }
    __syncthreads();
    for (int i = threadIdx.x; i < 1024; i += 256) {
        int r = i >> 5, c = i & 31;
        unsigned short h, l;
        split2(tile[r][c], h, l);
        int idx = (z * 512 + n0 + r) * 1024 + k0 + c;
        g_wth[idx] = h; g_wtl[idx] = l;
    }
}

__global__ __launch_bounds__(256) void split_wu_kernel(const float* __restrict__ Wu) {
    __shared__ float tile[32][33];
    const int n0 = blockIdx.x * 32, k0 = blockIdx.y * 32;
    for (int i = threadIdx.x; i < 1024; i += 256) {
        int r = i >> 5, c = i & 31;
        tile[c][r] = Wu[(k0 + r) * 64 + n0 + c];
    }
    __syncthreads();
    for (int i = threadIdx.x; i < 1024; i += 256) {
        int r = i >> 5, c = i & 31;
        unsigned short h, l;
        split2(tile[r][c], h, l);
        int idx = (n0 + r) * 512 + k0 + c;
        g_wuth[idx] = h; g_wutl[idx] = l;
    }
}

// ---------------------------------------------------------------------------
// QKV GEMM: [8192 x 1536] = Xsplit @ Wsplit^T, mma.sync bf16 3-split
// grid (12, 64), 256 threads (8 warps: 4m x 2n), CTA tile 128x128, k-chunk 64
// ---------------------------------------------------------------------------
#define QKV_SMEM (65536 + 1024)

__global__ __launch_bounds__(256) void qkv_mma_kernel() {
    extern __shared__ char smem_raw[];
    const uint32_t tb = (smem_u32(smem_raw) + 1023) & ~1023u;
    const int tid = threadIdx.x, lane = tid & 31, wid = tid >> 5;
    const int wm = wid >> 1, wn = wid & 1;
    const int n0 = blockIdx.x << 7, m0 = blockIdx.y << 7;

    float acc[2][8][4] = {};

    const int arow = wm * 32 + (lane & 7) + (((lane >> 3) & 1) << 3);
    const uint32_t acol = (lane >> 4) << 4;
    const int brow = wn * 64 + (lane & 7) + ((lane >> 4) << 3);
    const uint32_t bcol = ((lane >> 3) & 1) << 4;

    for (int chunk = 0; chunk < 16; chunk++) {
        const int k0 = chunk << 6;
        for (int o = tid; o < 4096; o += 256) {
            int tile = o >> 10, r = (o >> 3) & 127, c16 = o & 7;
            const unsigned short* src;
            if (tile == 0)      src = g_xh  + (size_t)(m0 + r) * 1024 + k0 + c16 * 8;
            else if (tile == 1) src = g_xl  + (size_t)(m0 + r) * 1024 + k0 + c16 * 8;
            else if (tile == 2) src = g_wth + (size_t)(n0 + r) * 1024 + k0 + c16 * 8;
            else                src = g_wtl + (size_t)(n0 + r) * 1024 + k0 + c16 * 8;
            cpa16(tb + (tile << 14) + swz((r << 7) + (c16 << 4)), src);
        }
        CPA_COMMIT(); CPA_WAIT0();
        __syncthreads();

#pragma unroll
        for (int k16 = 0; k16 < 4; k16++) {
            uint32_t ah[2][4], al[2][4];
#pragma unroll
            for (int mt = 0; mt < 2; mt++) {
                uint32_t off = swz(((arow + mt * 16) << 7) + k16 * 32 + acol);
                ldsm_x4(ah[mt], tb + off);
                ldsm_x4(al[mt], tb + 16384 + off);
            }
#pragma unroll
            for (int nt2 = 0; nt2 < 4; nt2++) {
                uint32_t off = swz(((brow + nt2 * 16) << 7) + k16 * 32 + bcol);
                uint32_t bh[4], bl[4];
                ldsm_x4(bh, tb + 32768 + off);
                ldsm_x4(bl, tb + 49152 + off);
#pragma unroll
                for (int mt = 0; mt < 2; mt++) {
                    mma_bf16(acc[mt][nt2 * 2],     ah[mt], bh[0], bh[1]);
                    mma_bf16(acc[mt][nt2 * 2],     ah[mt], bl[0], bl[1]);
                    mma_bf16(acc[mt][nt2 * 2],     al[mt], bh[0], bh[1]);
                    mma_bf16(acc[mt][nt2 * 2 + 1], ah[mt], bh[2], bh[3]);
                    mma_bf16(acc[mt][nt2 * 2 + 1], ah[mt], bl[2], bl[3]);
                    mma_bf16(acc[mt][nt2 * 2 + 1], al[mt], bh[2], bh[3]);
                }
            }
        }
        __syncthreads();
    }

    // Epilogue: split f32 acc -> bf16 hi/lo, scatter to [bh][t][hd]
    const int nbase = n0 + wn * 64;
    const int z = nbase >> 9;
    unsigned short* OH = (z == 0) ? g_qh : ((z == 1) ? g_kh : g_vh);
    unsigned short* OL = (z == 0) ? g_ql : ((z == 1) ? g_kl : g_vl);
#pragma unroll
    for (int mt = 0; mt < 2; mt++) {
#pragma unroll
        for (int nt = 0; nt < 8; nt++) {
            int col = nbase + nt * 8 + ((lane & 3) << 1);
            int rem = col & 511, h = rem >> 6, hd = rem & 63;
            int m = m0 + wm * 32 + mt * 16 + (lane >> 2);
            uint32_t hv, lv;
            int b = m >> 11, t = m & 2047;
            size_t idx = ((size_t)((b << 3) + h) * 2048 + t) * 64 + hd;
            split_pack(acc[mt][nt][0], acc[mt][nt][1], hv, lv);
            *(uint32_t*)&OH[idx] = hv; *(uint32_t*)&OL[idx] = lv;
            int m2 = m + 8; b = m2 >> 11; t = m2 & 2047;
            idx = ((size_t)((b << 3) + h) * 2048 + t) * 64 + hd;
            split_pack(acc[mt][nt][2], acc[mt][nt][3], hv, lv);
            *(uint32_t*)&OH[idx] = hv; *(uint32_t*)&OL[idx] = lv;
        }
    }
}

// ---------------------------------------------------------------------------
// Flash attention on mma.sync. grid (16, 32), 256 threads (8 warps x 16 q-rows)
// smem: Qh 16K | Ql 16K | Kh 8K | Kl 8K | Vh 8K | Vl 8K
// ---------------------------------------------------------------------------
#define ATT_SMEM (65536 + 1024)

__global__ __launch_bounds__(256) void attn_mma_kernel(const int* __restrict__ pads) {
    extern __shared__ char smem_raw[];
    const uint32_t tb = (smem_u32(smem_raw) + 1023) & ~1023u;
    const int tid = threadIdx.x, lane = tid & 31, wid = tid >> 5;
    const int bh = blockIdx.y, q0 = blockIdx.x << 7;
    const int wq = wid << 4;

    int thr = TT + 1;
    if (bh < BB) thr = TT - pads[bh];

    const size_t base = (size_t)bh * TT * HD;

    // Q tiles (committed with first K/V group)
    for (int o = tid; o < 2048; o += 256) {
        int tile = o >> 10, r = (o >> 3) & 127, c16 = o & 7;
        const unsigned short* src = (tile ? g_ql : g_qh) + base + (size_t)(q0 + r) * 64 + c16 * 8;
        cpa16(tb + (tile << 14) + swz((r << 7) + (c16 << 4)), src);
    }

    float o_[8][4] = {};
    float mi0 = -1e30f, mi1 = -1e30f, li0 = 0.f, li1 = 0.f;

    const int row0 = q0 + wq + (lane >> 2);
    const int row1 = row0 + 8;

    const int arow = wq + (lane & 7) + (((lane >> 3) & 1) << 3);
    const uint32_t acol = (lane >> 4) << 4;
    const int brow = (lane & 7) + ((lane >> 4) << 3);
    const uint32_t bcol = ((lane >> 3) & 1) << 4;
    const int vkey = (lane & 7) + (((lane >> 3) & 1) << 3);
    const uint32_t vcol = (lane >> 4) << 4;

    for (int kt = 0; kt < 32; kt++) {
        for (int o = tid; o < 2048; o += 256) {
            int tile = o >> 9, r = (o >> 3) & 63, c16 = o & 7;
            const unsigned short* sel =
                (tile == 0) ? g_kh : ((tile == 1) ? g_kl : ((tile == 2) ? g_vh : g_vl));
            const unsigned short* src = sel + base + (size_t)(kt * 64 + r) * 64 + c16 * 8;
            cpa16(tb + 32768 + (tile << 13) + swz((r << 7) + (c16 << 4)), src);
        }
        CPA_COMMIT(); CPA_WAIT0();
        __syncthreads();

        // ---- S = Q K^T ----
        float s[8][4] = {};
#pragma unroll
        for (int k16 = 0; k16 < 4; k16++) {
            uint32_t ah[4], al[4];
            uint32_t offa = swz((arow << 7) + k16 * 32 + acol);
            ldsm_x4(ah, tb + offa);
            ldsm_x4(al, tb + 16384 + offa);
#pragma unroll
            for (int nt2 = 0; nt2 < 4; nt2++) {
                uint32_t offb = swz(((brow + nt2 * 16) << 7) + k16 * 32 + bcol);
                uint32_t kh[4], kl[4];
                ldsm_x4(kh, tb + 32768 + offb);
                ldsm_x4(kl, tb + 40960 + offb);
                mma_bf16(s[nt2 * 2],     ah, kh[0], kh[1]);
                mma_bf16(s[nt2 * 2],     ah, kl[0], kl[1]);
                mma_bf16(s[nt2 * 2],     al, kh[0], kh[1]);
                mma_bf16(s[nt2 * 2 + 1], ah, kh[2], kh[3]);
                mma_bf16(s[nt2 * 2 + 1], ah, kl[2], kl[3]);
                mma_bf16(s[nt2 * 2 + 1], al, kh[2], kh[3]);
            }
        }

        // ---- mask ----
        if (kt * 64 + 63 >= thr) {
            int cb = kt * 64 + ((lane & 3) << 1);
#pragma unroll
            for (int nt = 0; nt < 8; nt++) {
                int c = cb + nt * 8;
                if (row0 >= thr) { if (c >= thr) s[nt][0] = -1e30f; if (c + 1 >= thr) s[nt][1] = -1e30f; }
                if (row1 >= thr) { if (c >= thr) s[nt][2] = -1e30f; if (c + 1 >= thr) s[nt][3] = -1e30f; }
            }
        }

        // ---- online softmax (rows: lane>>2 and +8; reduce over lane-xor 1,2) ----
        float mx0 = -1e30f, mx1 = -1e30f;
#pragma unroll
        for (int nt = 0; nt < 8; nt++) {
            mx0 = fmaxf(mx0, fmaxf(s[nt][0], s[nt][1]));
            mx1 = fmaxf(mx1, fmaxf(s[nt][2], s[nt][3]));
        }
        mx0 = fmaxf(mx0, __shfl_xor_sync(0xffffffffu, mx0, 1));
        mx0 = fmaxf(mx0, __shfl_xor_sync(0xffffffffu, mx0, 2));
        mx1 = fmaxf(mx1, __shfl_xor_sync(0xffffffffu, mx1, 1));
        mx1 = fmaxf(mx1, __shfl_xor_sync(0xffffffffu, mx1, 2));
        float mn0 = fmaxf(mi0, mx0), mn1 = fmaxf(mi1, mx1);
        float a0 = __expf(mi0 - mn0), a1 = __expf(mi1 - mn1);
        float sum0 = 0.f, sum1 = 0.f;
#pragma unroll
        for (int nt = 0; nt < 8; nt++) {
            s[nt][0] = __expf(s[nt][0] - mn0); sum0 += s[nt][0];
            s[nt][1] = __expf(s[nt][1] - mn0); sum0 += s[nt][1];
            s[nt][2] = __expf(s[nt][2] - mn1); sum1 += s[nt][2];
            s[nt][3] = __expf(s[nt][3] - mn1); sum1 += s[nt][3];
        }
        sum0 += __shfl_xor_sync(0xffffffffu, sum0, 1);
        sum0 += __shfl_xor_sync(0xffffffffu, sum0, 2);
        sum1 += __shfl_xor_sync(0xffffffffu, sum1, 1);
        sum1 += __shfl_xor_sync(0xffffffffu, sum1, 2);
        li0 = li0 * a0 + sum0; li1 = li1 * a1 + sum1;
        mi0 = mn0; mi1 = mn1;
#pragma unroll
        for (int nt = 0; nt < 8; nt++) {
            o_[nt][0] *= a0; o_[nt][1] *= a0; o_[nt][2] *= a1; o_[nt][3] *= a1;
        }

        // ---- O += P V  (P repacked from S fragments, hi/lo split in regs) ----
#pragma unroll
        for (int k16 = 0; k16 < 4; k16++) {
            uint32_t ph[4], pl[4];
            split_pack(s[k16 * 2][0],     s[k16 * 2][1],     ph[0], pl[0]);
            split_pack(s[k16 * 2][2],     s[k16 * 2][3],     ph[1], pl[1]);
            split_pack(s[k16 * 2 + 1][0], s[k16 * 2 + 1][1], ph[2], pl[2]);
            split_pack(s[k16 * 2 + 1][2], s[k16 * 2 + 1][3], ph[3], pl[3]);
#pragma unroll
            for (int ht2 = 0; ht2 < 4; ht2++) {
                uint32_t offv = swz(((k16 * 16 + vkey) << 7) + ht2 * 32 + vcol);
                uint32_t vh[4], vl[4];
                ldsm_x4_t(vh, tb + 49152 + offv);
                ldsm_x4_t(vl, tb + 57344 + offv);
                mma_bf16(o_[ht2 * 2],     ph, vh[0], vh[1]);
                mma_bf16(o_[ht2 * 2],     ph, vl[0], vl[1]);
                mma_bf16(o_[ht2 * 2],     pl, vh[0], vh[1]);
                mma_bf16(o_[ht2 * 2 + 1], ph, vh[2], vh[3]);
                mma_bf16(o_[ht2 * 2 + 1], ph, vl[2], vl[3]);
                mma_bf16(o_[ht2 * 2 + 1], pl, vh[2], vh[3]);
            }
        }
        __syncthreads();
    }

    // ---- epilogue: O/l, split to bf16 hi/lo for the out-proj ----
    float inv0 = 1.f / li0, inv1 = 1.f / li1;
    const int b = bh >> 3, h = bh & 7;
    const int t0 = q0 + wq + (lane >> 2), t1 = t0 + 8;
#pragma unroll
    for (int nt = 0; nt < 8; nt++) {
        int hd = nt * 8 + ((lane & 3) << 1);
        uint32_t hv, lv;
        size_t i0 = ((size_t)(b * TT + t0)) * 512 + h * 64 + hd;
        split_pack(o_[nt][0] * inv0, o_[nt][1] * inv0, hv, lv);
        *(uint32_t*)&g_ah[i0] = hv; *(uint32_t*)&g_al[i0] = lv;
        size_t i1 = ((size_t)(b * TT + t1)) * 512 + h * 64 + hd;
        split_pack(o_[nt][2] * inv1, o_[nt][3] * inv1, hv, lv);
        *(uint32_t*)&g_ah[i1] = hv; *(uint32_t*)&g_al[i1] = lv;
    }
}

// ---------------------------------------------------------------------------
// Out projection: [8192 x 64] = att @ Wu + bu. grid (64), 256 threads.
// ---------------------------------------------------------------------------
#define PROJ_SMEM (49152 + 1024)

__global__ __launch_bounds__(256) void proj_mma_kernel(const float* __restrict__ bu,
                                                       float* __restrict__ out) {
    extern __shared__ char smem_raw[];
    const uint32_t tb = (smem_u32(smem_raw) + 1023) & ~1023u;
    const int tid = threadIdx.x, lane = tid & 31, wid = tid >> 5;
    const int m0 = blockIdx.x << 7;

    float acc[8][4] = {};

    const int arow = wid * 16 + (lane & 7) + (((lane >> 3) & 1) << 3);
    const uint32_t acol = (lane >> 4) << 4;
    const int brow = (lane & 7) + ((lane >> 4) << 3);
    const uint32_t bcol = ((lane >> 3) & 1) << 4;

    for (int chunk = 0; chunk < 8; chunk++) {
        const int k0 = chunk << 6;
        for (int o = tid; o < 3072; o += 256) {
            const unsigned short* src;
            uint32_t dst;
            if (o < 2048) {
                int tile = o >> 10, r = (o >> 3) & 127, c16 = o & 7;
                src = (tile ? g_al : g_ah) + (size_t)(m0 + r) * 512 + k0 + c16 * 8;
                dst = tb + (tile << 14) + swz((r << 7) + (c16 << 4));
            } else {
                int o2 = o - 2048;
                int tile = o2 >> 9, r = (o2 >> 3) & 63, c16 = o2 & 7;
                src = (tile ? g_wutl : g_wuth) + (size_t)r * 512 + k0 + c16 * 8;
                dst = tb + 32768 + (tile << 13) + swz((r << 7) + (c16 << 4));
            }
            cpa16(dst, src);
        }
        CPA_COMMIT(); CPA_WAIT0();
        __syncthreads();

#pragma unroll
        for (int k16 = 0; k16 < 4; k16++) {
            uint32_t ah[4], al[4];
            uint32_t offa = swz((arow << 7) + k16 * 32 + acol);
            ldsm_x4(ah, tb + offa);
            ldsm_x4(al, tb + 16384 + offa);
#pragma unroll
            for (int nt2 = 0; nt2 < 4; nt2++) {
                uint32_t offb = swz(((brow + nt2 * 16) << 7) + k16 * 32 + bcol);
                uint32_t bh2[4], bl2[4];
                ldsm_x4(bh2, tb + 32768 + offb);
                ldsm_x4(bl2, tb + 40960 + offb);
                mma_bf16(acc[nt2 * 2],     ah, bh2[0], bh2[1]);
                mma_bf16(acc[nt2 * 2],     ah, bl2[0], bl2[1]);
                mma_bf16(acc[nt2 * 2],     al, bh2[0], bh2[1]);
                mma_bf16(acc[nt2 * 2 + 1], ah, bh2[2], bh2[3]);
                mma_bf16(acc[nt2 * 2 + 1], ah, bl2[2], bl2[3]);
                mma_bf16(acc[nt2 * 2 + 1], al, bh2[2], bh2[3]);
            }
        }
        __syncthreads();
    }

    const int m = m0 + wid * 16 + (lane >> 2);
#pragma unroll
    for (int nt = 0; nt < 8; nt++) {
        int col = nt * 8 + ((lane & 3) << 1);
        float b0 = bu[col], b1 = bu[col + 1];
        *(float2*)&out[(size_t)m * 64 + col] =
            make_float2(acc[nt][0] + b0, acc[nt][1] + b1);
        *(float2*)&out[(size_t)(m + 8) * 64 + col] =
            make_float2(acc[nt][2] + b0, acc[nt][3] + b1);
    }
}

// ---------------------------------------------------------------------------
extern "C" void kernel_launch(void* const* d_in, const int* in_sizes, int n_in,
                              void* d_out, int out_size)
{
    (void)in_sizes; (void)n_in; (void)out_size;
    const float* x    = (const float*)d_in[0];
    const int*   pads = (const int*)  d_in[1];
    const float* Wq   = (const float*)d_in[2];
    const float* Wk   = (const float*)d_in[3];
    const float* Wv   = (const float*)d_in[4];
    const float* Wu   = (const float*)d_in[5];
    const float* bu   = (const float*)d_in[6];
    float* out = (float*)d_out;

    cudaFuncSetAttribute(qkv_mma_kernel,  cudaFuncAttributeMaxDynamicSharedMemorySize, QKV_SMEM);
    cudaFuncSetAttribute(attn_mma_kernel, cudaFuncAttributeMaxDynamicSharedMemorySize, ATT_SMEM);
    cudaFuncSetAttribute(proj_mma_kernel, cudaFuncAttributeMaxDynamicSharedMemorySize, PROJ_SMEM);

    split_x_kernel<<<8192, 256>>>(x);
    split_w_kernel<<<dim3(16, 32, 3), 256>>>(Wq, Wk, Wv);
    split_wu_kernel<<<dim3(2, 16), 256>>>(Wu);

    qkv_mma_kernel<<<dim3(12, 64), 256, QKV_SMEM>>>();
    attn_mma_kernel<<<dim3(16, 32), 256, ATT_SMEM>>>(pads);
    proj_mma_kernel<<<64, 256, PROJ_SMEM>>>(bu, out);
}